// round 1
// baseline (speedup 1.0000x reference)
#include <cuda_runtime.h>
#include <cuda_bf16.h>

// ---------------------------------------------------------------------------
// GIN layer: out = relu( relu( (x + scatter_sum(x[src] -> dst)) @ W1^T + b1 ) @ W2^T + b2 )
// N = 100000 nodes, D = 128, E = 625000 edges.
//
// Plan:
//   K1: agg = x                       (vectorized copy; folds (1+eps)*x, eps=0)
//   K2: agg[dst] += x[src]            (1 warp per edge, red.global.add.v4.f32)
//   K3: fused MLP, 128-row tiles      (W1^T, W2^T, A-tile in smem; h1 never hits gmem)
// ---------------------------------------------------------------------------

#define D 128
#define MAX_N 100000

// scratch for aggregated features (allocation-free contract -> device global)
__device__ float g_agg[(size_t)MAX_N * D];

// ---------------------------------------------------------------------------
__global__ void copy_x_kernel(const float* __restrict__ x, int total4) {
    int i = blockIdx.x * blockDim.x + threadIdx.x;
    if (i < total4) {
        ((float4*)g_agg)[i] = ((const float4*)x)[i];
    }
}

// ---------------------------------------------------------------------------
// One warp per edge; each lane handles 4 floats via a 16B vector reduction.
__global__ void scatter_kernel(const float* __restrict__ x,
                               const int* __restrict__ src,
                               const int* __restrict__ dst,
                               int E) {
    long tid = (long)blockIdx.x * blockDim.x + threadIdx.x;
    int e    = (int)(tid >> 5);
    int lane = (int)(tid & 31);
    if (e >= E) return;
    int s = src[e];          // uniform across warp -> broadcast load
    int d = dst[e];
    const float4 v = *(const float4*)(x + (long)s * D + lane * 4);
    float* p = g_agg + (long)d * D + lane * 4;
    asm volatile("red.global.add.v4.f32 [%0], {%1, %2, %3, %4};"
                 :: "l"(p), "f"(v.x), "f"(v.y), "f"(v.z), "f"(v.w)
                 : "memory");
}

// ---------------------------------------------------------------------------
// Fused 2-layer MLP. Block = 256 threads handles 128 rows x 128 cols.
// smem: Abuf[128][132] (A tile, then h1 tile), W1t[128][132], W2t[128][132]
//   Wt[m][nn] = W[nn][m]  so the k-loop reads Wt[k][*] conflict-free.
// Thread (tx,ty), tx in [0,16), ty in [0,16):
//   rows i = ty + 16*r (r<8), cols nn = tx + 16*c (c<8)  -> 8x8 register tile.
#define SMSTRIDE 132

__global__ __launch_bounds__(256, 1)
void mlp_kernel(const float* __restrict__ W1, const float* __restrict__ b1,
                const float* __restrict__ W2, const float* __restrict__ b2,
                float* __restrict__ out, int n) {
    extern __shared__ float sm[];
    float* Abuf = sm;                       // 128*132
    float* W1t  = sm + 128 * SMSTRIDE;      // 128*132
    float* W2t  = W1t + 128 * SMSTRIDE;     // 128*132

    const int tid = threadIdx.x;
    const int tx  = tid & 15;
    const int ty  = tid >> 4;
    const int row0 = blockIdx.x * 128;

    // Load both weight matrices transposed into smem.
    for (int idx = tid; idx < D * D; idx += 256) {
        int nn = idx >> 7;          // output-feature index (row of W)
        int m  = idx & 127;         // input-feature index  (col of W)
        W1t[m * SMSTRIDE + nn] = W1[idx];
        W2t[m * SMSTRIDE + nn] = W2[idx];
    }

    // Load A tile (128 rows x 128 cols) as float4s; zero-pad past n.
    for (int j = tid; j < 128 * 32; j += 256) {
        int i  = j >> 5;
        int k4 = j & 31;
        int row = row0 + i;
        float4 v = make_float4(0.f, 0.f, 0.f, 0.f);
        if (row < n) v = *(const float4*)(g_agg + (long)row * D + k4 * 4);
        *(float4*)(Abuf + i * SMSTRIDE + k4 * 4) = v;
    }

    // Per-thread bias fragments.
    float bb1[8], bb2[8];
#pragma unroll
    for (int c = 0; c < 8; ++c) {
        bb1[c] = b1[tx + 16 * c];
        bb2[c] = b2[tx + 16 * c];
    }

    __syncthreads();

    float acc[8][8];
#pragma unroll
    for (int r = 0; r < 8; ++r)
#pragma unroll
        for (int c = 0; c < 8; ++c) acc[r][c] = 0.f;

    // ---- GEMM 1: acc = A @ W1^T ----
#pragma unroll 4
    for (int k = 0; k < D; ++k) {
        float a[8], w[8];
#pragma unroll
        for (int r = 0; r < 8; ++r) a[r] = Abuf[(ty + 16 * r) * SMSTRIDE + k];
#pragma unroll
        for (int c = 0; c < 8; ++c) w[c] = W1t[k * SMSTRIDE + tx + 16 * c];
#pragma unroll
        for (int r = 0; r < 8; ++r)
#pragma unroll
            for (int c = 0; c < 8; ++c) acc[r][c] += a[r] * w[c];
    }

    __syncthreads();   // everyone done reading Abuf

    // bias + relu -> write h1 back into Abuf
#pragma unroll
    for (int r = 0; r < 8; ++r)
#pragma unroll
        for (int c = 0; c < 8; ++c) {
            float v = acc[r][c] + bb1[c];
            v = fmaxf(v, 0.f);
            Abuf[(ty + 16 * r) * SMSTRIDE + tx + 16 * c] = v;
            acc[r][c] = 0.f;
        }

    __syncthreads();

    // ---- GEMM 2: acc = h1 @ W2^T ----
#pragma unroll 4
    for (int k = 0; k < D; ++k) {
        float a[8], w[8];
#pragma unroll
        for (int r = 0; r < 8; ++r) a[r] = Abuf[(ty + 16 * r) * SMSTRIDE + k];
#pragma unroll
        for (int c = 0; c < 8; ++c) w[c] = W2t[k * SMSTRIDE + tx + 16 * c];
#pragma unroll
        for (int r = 0; r < 8; ++r)
#pragma unroll
            for (int c = 0; c < 8; ++c) acc[r][c] += a[r] * w[c];
    }

    // bias + relu -> global
#pragma unroll
    for (int r = 0; r < 8; ++r) {
        int row = row0 + ty + 16 * r;
        if (row < n) {
#pragma unroll
            for (int c = 0; c < 8; ++c) {
                float v = acc[r][c] + bb2[c];
                out[(long)row * D + tx + 16 * c] = fmaxf(v, 0.f);
            }
        }
    }
}

// ---------------------------------------------------------------------------
extern "C" void kernel_launch(void* const* d_in, const int* in_sizes, int n_in,
                              void* d_out, int out_size) {
    const float* x  = (const float*)d_in[0];
    const int*   ei = (const int*)d_in[1];
    const float* W1 = (const float*)d_in[2];
    const float* b1 = (const float*)d_in[3];
    const float* W2 = (const float*)d_in[4];
    const float* b2 = (const float*)d_in[5];
    float* out = (float*)d_out;

    const int n = in_sizes[0] / D;          // number of nodes
    const int E = in_sizes[1] / 2;          // number of edges
    const int* src = ei;
    const int* dst = ei + E;

    // K1: agg = x
    {
        int total4 = n * (D / 4);
        int blocks = (total4 + 255) / 256;
        copy_x_kernel<<<blocks, 256>>>(x, total4);
    }

    // K2: scatter-add
    {
        long threads = (long)E * 32;
        int blocks = (int)((threads + 255) / 256);
        scatter_kernel<<<blocks, 256>>>(x, src, dst, E);
    }

    // K3: fused MLP
    {
        int smem = 3 * 128 * SMSTRIDE * (int)sizeof(float);   // 202752 B
        cudaFuncSetAttribute(mlp_kernel,
                             cudaFuncAttributeMaxDynamicSharedMemorySize, smem);
        int blocks = (n + 127) / 128;
        mlp_kernel<<<blocks, 256, smem>>>(W1, b1, W2, b2, out, n);
    }
}

// round 2
// speedup vs baseline: 1.4407x; 1.4407x over previous
#include <cuda_runtime.h>
#include <cuda_bf16.h>

// ---------------------------------------------------------------------------
// GIN layer: out = relu( relu( (x + scatter_sum(x[src] -> dst)) @ W1^T + b1 ) @ W2^T + b2 )
// N = 100000, D = 128, E = 625000.
//
//   K1: agg = 0                        (zero-fill; x folded into MLP input)
//   K2: agg[dst] += x[src]             (1 warp/edge, red.global.add.v4.f32)
//   K3: fused MLP with tf32 mma.sync   (A = x + agg; h1 in smem; 2 GEMMs fused)
// ---------------------------------------------------------------------------

#define D 128
#define MAX_N 100000
#define SA 132   // Abuf row stride (floats): bank = 4*row'+k' -> conflict-free frags
#define SB 136   // W row stride   (floats): bank = 8*k'+n'   -> conflict-free frags

__device__ float g_agg[(size_t)MAX_N * D];

// ---------------------------------------------------------------------------
__global__ void zero_agg_kernel(int total4) {
    int i = blockIdx.x * blockDim.x + threadIdx.x;
    if (i < total4) ((float4*)g_agg)[i] = make_float4(0.f, 0.f, 0.f, 0.f);
}

// ---------------------------------------------------------------------------
__global__ void scatter_kernel(const float* __restrict__ x,
                               const int* __restrict__ src,
                               const int* __restrict__ dst,
                               int E) {
    long tid = (long)blockIdx.x * blockDim.x + threadIdx.x;
    int e    = (int)(tid >> 5);
    int lane = (int)(tid & 31);
    if (e >= E) return;
    int s = src[e];
    int d = dst[e];
    const float4 v = *(const float4*)(x + (long)s * D + lane * 4);
    float* p = g_agg + (long)d * D + lane * 4;
    asm volatile("red.global.add.v4.f32 [%0], {%1, %2, %3, %4};"
                 :: "l"(p), "f"(v.x), "f"(v.y), "f"(v.z), "f"(v.w)
                 : "memory");
}

// ---------------------------------------------------------------------------
__device__ __forceinline__ unsigned f2tf32(float f) {
    unsigned r;
    asm("cvt.rna.tf32.f32 %0, %1;" : "=r"(r) : "f"(f));
    return r;
}

__device__ __forceinline__ void mma_tf32(float c[4], const unsigned a[4],
                                         const unsigned b[2]) {
    asm volatile(
        "mma.sync.aligned.m16n8k8.row.col.f32.tf32.tf32.f32 "
        "{%0,%1,%2,%3}, {%4,%5,%6,%7}, {%8,%9}, {%0,%1,%2,%3};"
        : "+f"(c[0]), "+f"(c[1]), "+f"(c[2]), "+f"(c[3])
        : "r"(a[0]), "r"(a[1]), "r"(a[2]), "r"(a[3]), "r"(b[0]), "r"(b[1]));
}

// ---------------------------------------------------------------------------
// Block: 256 threads (8 warps) -> 128 rows x 128 cols tile.
// Warp tile: 32 rows x 64 cols (2 m-tiles x 8 n-tiles of m16n8k8).
// smem: Abuf[128][SA] (A tile / h1 tile, tf32 bits), W1t/W2t[128][SB] (W^T, tf32).
__global__ __launch_bounds__(256, 1)
void mlp_kernel(const float* __restrict__ x,
                const float* __restrict__ W1, const float* __restrict__ b1,
                const float* __restrict__ W2, const float* __restrict__ b2,
                float* __restrict__ out, int n) {
    extern __shared__ float sm[];
    float* Abuf = sm;                     // 128*SA
    float* W1t  = sm + 128 * SA;          // 128*SB
    float* W2t  = W1t + 128 * SB;         // 128*SB

    const int tid  = threadIdx.x;
    const int w    = tid >> 5;
    const int lane = tid & 31;
    const int lr   = lane >> 2;   // 0..7  (groupID)
    const int lc   = lane & 3;    // 0..3  (threadID_in_group)
    const int rw   = (w & 3) * 32;    // warp row offset in tile
    const int cw   = (w >> 2) * 64;   // warp col offset in tile
    const int row0 = blockIdx.x * 128;

    // Load W1^T, W2^T into smem as tf32. Wt[m][nn] = W[nn][m].
    for (int idx = tid; idx < D * D; idx += 256) {
        int nn = idx >> 7;        // output feature (row of W)
        int m  = idx & 127;       // input feature  (col of W)
        W1t[m * SB + nn] = __uint_as_float(f2tf32(W1[idx]));
        W2t[m * SB + nn] = __uint_as_float(f2tf32(W2[idx]));
    }

    // Load A tile: A = x + agg, converted to tf32.
    {
        int i  = tid >> 5;              // 0..7 (row group start)
        int k4 = tid & 31;              // 0..31 (float4 index)
        for (int ii = i; ii < 128; ii += 8) {
            int row = row0 + ii;
            float4 v = make_float4(0.f, 0.f, 0.f, 0.f);
            if (row < n) {
                float4 vx = *(const float4*)(x + (long)row * D + k4 * 4);
                float4 vg = *(const float4*)(g_agg + (long)row * D + k4 * 4);
                v.x = vx.x + vg.x; v.y = vx.y + vg.y;
                v.z = vx.z + vg.z; v.w = vx.w + vg.w;
            }
            uint4 t;
            t.x = f2tf32(v.x); t.y = f2tf32(v.y);
            t.z = f2tf32(v.z); t.w = f2tf32(v.w);
            *(uint4*)(Abuf + ii * SA + k4 * 4) = t;
        }
    }
    __syncthreads();

    float acc[2][8][4];
#pragma unroll
    for (int mt = 0; mt < 2; ++mt)
#pragma unroll
        for (int nt = 0; nt < 8; ++nt)
#pragma unroll
            for (int q = 0; q < 4; ++q) acc[mt][nt][q] = 0.f;

    // ---- GEMM 1: acc = A @ W1^T ----
#pragma unroll 4
    for (int ks = 0; ks < 16; ++ks) {
        const int k0 = ks * 8;
        unsigned a[2][4];
#pragma unroll
        for (int mt = 0; mt < 2; ++mt) {
            const float* p = Abuf + (rw + 16 * mt + lr) * SA + k0 + lc;
            a[mt][0] = __float_as_uint(p[0]);
            a[mt][1] = __float_as_uint(p[8 * SA]);
            a[mt][2] = __float_as_uint(p[4]);
            a[mt][3] = __float_as_uint(p[8 * SA + 4]);
        }
        unsigned b[8][2];
#pragma unroll
        for (int nt = 0; nt < 8; ++nt) {
            const float* p = W1t + (k0 + lc) * SB + cw + 8 * nt + lr;
            b[nt][0] = __float_as_uint(p[0]);
            b[nt][1] = __float_as_uint(p[4 * SB]);
        }
#pragma unroll
        for (int mt = 0; mt < 2; ++mt)
#pragma unroll
            for (int nt = 0; nt < 8; ++nt) mma_tf32(acc[mt][nt], a[mt], b[nt]);
    }
    __syncthreads();   // everyone done reading Abuf

    // Epilogue 1: bias + relu -> h1 (tf32) back into Abuf.
#pragma unroll
    for (int mt = 0; mt < 2; ++mt) {
#pragma unroll
        for (int nt = 0; nt < 8; ++nt) {
            int col = cw + 8 * nt + 2 * lc;
            int r_a = rw + 16 * mt + lr;
            float bc0 = b1[col], bc1 = b1[col + 1];
            uint2 u0, u1;
            u0.x = f2tf32(fmaxf(acc[mt][nt][0] + bc0, 0.f));
            u0.y = f2tf32(fmaxf(acc[mt][nt][1] + bc1, 0.f));
            u1.x = f2tf32(fmaxf(acc[mt][nt][2] + bc0, 0.f));
            u1.y = f2tf32(fmaxf(acc[mt][nt][3] + bc1, 0.f));
            *(uint2*)(Abuf + r_a * SA + col)       = u0;
            *(uint2*)(Abuf + (r_a + 8) * SA + col) = u1;
            acc[mt][nt][0] = acc[mt][nt][1] = 0.f;
            acc[mt][nt][2] = acc[mt][nt][3] = 0.f;
        }
    }
    __syncthreads();

    // ---- GEMM 2: acc = h1 @ W2^T ----
#pragma unroll 4
    for (int ks = 0; ks < 16; ++ks) {
        const int k0 = ks * 8;
        unsigned a[2][4];
#pragma unroll
        for (int mt = 0; mt < 2; ++mt) {
            const float* p = Abuf + (rw + 16 * mt + lr) * SA + k0 + lc;
            a[mt][0] = __float_as_uint(p[0]);
            a[mt][1] = __float_as_uint(p[8 * SA]);
            a[mt][2] = __float_as_uint(p[4]);
            a[mt][3] = __float_as_uint(p[8 * SA + 4]);
        }
        unsigned b[8][2];
#pragma unroll
        for (int nt = 0; nt < 8; ++nt) {
            const float* p = W2t + (k0 + lc) * SB + cw + 8 * nt + lr;
            b[nt][0] = __float_as_uint(p[0]);
            b[nt][1] = __float_as_uint(p[4 * SB]);
        }
#pragma unroll
        for (int mt = 0; mt < 2; ++mt)
#pragma unroll
            for (int nt = 0; nt < 8; ++nt) mma_tf32(acc[mt][nt], a[mt], b[nt]);
    }

    // Epilogue 2: bias + relu -> global.
#pragma unroll
    for (int mt = 0; mt < 2; ++mt) {
#pragma unroll
        for (int nt = 0; nt < 8; ++nt) {
            int col = cw + 8 * nt + 2 * lc;
            int r_a = rw + 16 * mt + lr;
            float bc0 = b2[col], bc1 = b2[col + 1];
            int row = row0 + r_a;
            if (row < n) {
                float2 v;
                v.x = fmaxf(acc[mt][nt][0] + bc0, 0.f);
                v.y = fmaxf(acc[mt][nt][1] + bc1, 0.f);
                *(float2*)(out + (long)row * D + col) = v;
            }
            if (row + 8 < n) {
                float2 v;
                v.x = fmaxf(acc[mt][nt][2] + bc0, 0.f);
                v.y = fmaxf(acc[mt][nt][3] + bc1, 0.f);
                *(float2*)(out + (long)(row + 8) * D + col) = v;
            }
        }
    }
}

// ---------------------------------------------------------------------------
extern "C" void kernel_launch(void* const* d_in, const int* in_sizes, int n_in,
                              void* d_out, int out_size) {
    const float* x  = (const float*)d_in[0];
    const int*   ei = (const int*)d_in[1];
    const float* W1 = (const float*)d_in[2];
    const float* b1 = (const float*)d_in[3];
    const float* W2 = (const float*)d_in[4];
    const float* b2 = (const float*)d_in[5];
    float* out = (float*)d_out;

    const int n = in_sizes[0] / D;
    const int E = in_sizes[1] / 2;
    const int* src = ei;
    const int* dst = ei + E;

    // K1: agg = 0
    {
        int total4 = n * (D / 4);
        int blocks = (total4 + 255) / 256;
        zero_agg_kernel<<<blocks, 256>>>(total4);
    }

    // K2: scatter-add
    {
        long threads = (long)E * 32;
        int blocks = (int)((threads + 255) / 256);
        scatter_kernel<<<blocks, 256>>>(x, src, dst, E);
    }

    // K3: fused tf32 MLP
    {
        int smem = (128 * SA + 2 * 128 * SB) * (int)sizeof(float);  // 206848 B
        cudaFuncSetAttribute(mlp_kernel,
                             cudaFuncAttributeMaxDynamicSharedMemorySize, smem);
        int blocks = (n + 127) / 128;
        mlp_kernel<<<blocks, 256, smem>>>(x, W1, b1, W2, b2, out, n);
    }
}